// round 1
// baseline (speedup 1.0000x reference)
#include <cuda_runtime.h>
#include <cuda_bf16.h>
#include <math.h>

// TorchGemma4VisionPooler: 2x2 average pooling over a dense 64x64 patch grid,
// scaled by sqrt(H). B=8, S=4096, H=1152, OUT_LEN=1024.
//
// out[b, oy*32+ox, h] = (in[b, (2oy)*64+2ox, h] + in[b, (2oy)*64+2ox+1, h]
//                      + in[b, (2oy+1)*64+2ox, h] + in[b, (2oy+1)*64+2ox+1, h])
//                      * sqrt(1152) / 4
//
// Pure HBM-bound: 151 MB read + 38 MB write, every element touched once.
// One thread per output float4 -> coalesced 4x16B reads + 1x16B write.

static constexpr int B_ = 8;
static constexpr int GRID_ = 64;
static constexpr int S_ = GRID_ * GRID_;     // 4096
static constexpr int H_ = 1152;
static constexpr int C4_ = H_ / 4;           // 288 float4 per row
static constexpr int OG_ = 32;               // output grid 32x32
static constexpr int L_ = OG_ * OG_;         // 1024
static constexpr int OUT_ELEMS_ = B_ * L_ * H_;  // 9437184

// sqrt(1152)/4
static constexpr float SCALE_ = 8.485281374238570f;

__global__ void pool2x2_kernel(const float4* __restrict__ in,
                               float4* __restrict__ out) {
    int idx = blockIdx.x * blockDim.x + threadIdx.x;
    constexpr int total = B_ * L_ * C4_;
    if (idx >= total) return;

    int c   = idx % C4_;
    int row = idx / C4_;        // b*L + o
    int o   = row % L_;
    int b   = row / L_;
    int ox  = o & (OG_ - 1);    // o % 32
    int oy  = o >> 5;           // o / 32

    // top-left source patch index in the 64x64 grid
    int s0 = (oy * 2) * GRID_ + ox * 2;

    const float4* base = in + ((size_t)b * S_ + s0) * C4_ + c;

    float4 a0 = __ldg(base);                     // (2ox,   2oy)
    float4 a1 = __ldg(base + C4_);               // (2ox+1, 2oy)
    float4 a2 = __ldg(base + (size_t)GRID_ * C4_);       // (2ox,   2oy+1)
    float4 a3 = __ldg(base + (size_t)(GRID_ + 1) * C4_); // (2ox+1, 2oy+1)

    float4 r;
    r.x = (a0.x + a1.x + a2.x + a3.x) * SCALE_;
    r.y = (a0.y + a1.y + a2.y + a3.y) * SCALE_;
    r.z = (a0.z + a1.z + a2.z + a3.z) * SCALE_;
    r.w = (a0.w + a1.w + a2.w + a3.w) * SCALE_;

    out[idx] = r;
}

// Fill the tail of d_out (beyond the pooled tensor) with 1.0f — the mask is
// all-true for the dense grid (every segment receives exactly k^2=4 patches).
__global__ void mask_fill_kernel(float* __restrict__ out, int n) {
    int idx = blockIdx.x * blockDim.x + threadIdx.x;
    if (idx < n) out[idx] = 1.0f;
}

extern "C" void kernel_launch(void* const* d_in, const int* in_sizes, int n_in,
                              void* d_out, int out_size) {
    const float4* in = (const float4*)d_in[0];
    float4* out = (float4*)d_out;

    constexpr int total = B_ * L_ * C4_;   // threads over output float4s
    constexpr int threads = 256;
    constexpr int blocks = (total + threads - 1) / threads;
    pool2x2_kernel<<<blocks, threads>>>(in, out);

    if (out_size > OUT_ELEMS_) {
        int tail = out_size - OUT_ELEMS_;
        float* tail_ptr = (float*)d_out + OUT_ELEMS_;
        int tb = (tail + 255) / 256;
        mask_fill_kernel<<<tb, 256>>>(tail_ptr, tail);
    }
}

// round 2
// speedup vs baseline: 1.0559x; 1.0559x over previous
#include <cuda_runtime.h>
#include <cuda_bf16.h>
#include <math.h>

// TorchGemma4VisionPooler: 2x2 average pooling over a dense 64x64 patch grid,
// scaled by sqrt(H). B=8, S=4096, H=1152, OUT_LEN=1024.
//
// out[b, oy*32+ox, h] = (sum of 4 neighbor patches) * sqrt(1152)/4
// mask (tail of d_out, B*L floats) = 1.0 (every segment gets exactly 4 patches)
//
// HBM-bound: 151 MB read + 38 MB write, each element touched exactly once.
// One thread per output float4 -> coalesced 4x16B streaming reads + 16B write.
// Mask write fused into the same kernel (first 8192 threads) to avoid a
// second serialized launch (~3.6us measured in R1).

static constexpr int B_ = 8;
static constexpr int GRID_ = 64;
static constexpr int S_ = GRID_ * GRID_;     // 4096
static constexpr int H_ = 1152;
static constexpr int C4_ = H_ / 4;           // 288 float4 per row
static constexpr int OG_ = 32;               // output grid 32x32
static constexpr int L_ = OG_ * OG_;         // 1024
static constexpr int OUT_ELEMS_ = B_ * L_ * H_;  // 9437184
static constexpr int MASK_ELEMS_ = B_ * L_;      // 8192

// sqrt(1152)/4
static constexpr float SCALE_ = 8.485281374238570f;

__global__ void pool2x2_fused_kernel(const float4* __restrict__ in,
                                     float4* __restrict__ out,
                                     float* __restrict__ mask_tail,
                                     int write_mask) {
    int idx = blockIdx.x * blockDim.x + threadIdx.x;
    constexpr int total = B_ * L_ * C4_;
    if (idx >= total) return;

    int c   = idx % C4_;
    int row = idx / C4_;        // b*L + o
    int o   = row % L_;
    int b   = row / L_;
    int ox  = o & (OG_ - 1);    // o % 32
    int oy  = o >> 5;           // o / 32

    // top-left source patch index in the 64x64 grid
    int s0 = (oy * 2) * GRID_ + ox * 2;

    const float4* base = in + ((size_t)b * S_ + s0) * C4_ + c;

    // streaming loads: zero reuse, footprint >> L2 -> evict-first
    float4 a0 = __ldcs(base);                            // (2ox,   2oy)
    float4 a1 = __ldcs(base + C4_);                      // (2ox+1, 2oy)
    float4 a2 = __ldcs(base + (size_t)GRID_ * C4_);      // (2ox,   2oy+1)
    float4 a3 = __ldcs(base + (size_t)(GRID_ + 1) * C4_);// (2ox+1, 2oy+1)

    float4 r;
    r.x = (a0.x + a1.x + a2.x + a3.x) * SCALE_;
    r.y = (a0.y + a1.y + a2.y + a3.y) * SCALE_;
    r.z = (a0.z + a1.z + a2.z + a3.z) * SCALE_;
    r.w = (a0.w + a1.w + a2.w + a3.w) * SCALE_;

    __stcs(out + idx, r);

    // fused mask write: first MASK_ELEMS_ threads each write one 1.0f
    if (write_mask && idx < MASK_ELEMS_) {
        mask_tail[idx] = 1.0f;
    }
}

extern "C" void kernel_launch(void* const* d_in, const int* in_sizes, int n_in,
                              void* d_out, int out_size) {
    const float4* in = (const float4*)d_in[0];
    float4* out = (float4*)d_out;

    int write_mask = (out_size > OUT_ELEMS_) ? 1 : 0;
    float* mask_tail = (float*)d_out + OUT_ELEMS_;

    constexpr int total = B_ * L_ * C4_;   // threads over output float4s
    constexpr int threads = 256;
    constexpr int blocks = (total + threads - 1) / threads;
    pool2x2_fused_kernel<<<blocks, threads>>>(in, out, mask_tail, write_mask);
}

// round 3
// speedup vs baseline: 1.0656x; 1.0092x over previous
#include <cuda_runtime.h>
#include <cuda_bf16.h>
#include <math.h>

// TorchGemma4VisionPooler: 2x2 average pool over a dense 64x64 patch grid,
// scaled by sqrt(H). B=8, S=4096, H=1152, OUT_LEN=1024.
//
// R3: two output patches per thread -> 8 front-batched independent LDG.128s
// (MLP_p1=8) to push DRAM% from 75 toward the ~85% streaming ceiling.
// All loads/stores coalesced: lanes carry consecutive c, 288 % 32 == 0 so
// warps never straddle a row; each LDG covers a contiguous 512B segment.

static constexpr int B_ = 8;
static constexpr int GRID_ = 64;
static constexpr int S_ = GRID_ * GRID_;     // 4096
static constexpr int H_ = 1152;
static constexpr int C4_ = H_ / 4;           // 288 float4 per row
static constexpr int OG_ = 32;               // output grid 32x32
static constexpr int L_ = OG_ * OG_;         // 1024
static constexpr int OUT_ELEMS_ = B_ * L_ * H_;  // 9437184
static constexpr int MASK_ELEMS_ = B_ * L_;      // 8192

// sqrt(1152)/4
static constexpr float SCALE_ = 8.485281374238570f;

__global__ __launch_bounds__(256)
void pool2x2_x2_kernel(const float4* __restrict__ in,
                       float4* __restrict__ out,
                       float* __restrict__ mask_tail,
                       int write_mask) {
    int idx = blockIdx.x * blockDim.x + threadIdx.x;
    constexpr int total_pairs = B_ * (L_ / 2) * C4_;   // 1,179,648
    if (idx >= total_pairs) return;

    int c = idx % C4_;
    int r = idx / C4_;          // r in [0, B*512)
    int op = r % (L_ / 2);      // output-pair index in [0,512)
    int b  = r / (L_ / 2);

    int o0 = op * 2;            // even output index; o1 = o0+1 shares oy
    int ox = o0 & (OG_ - 1);    // even, in [0,30]
    int oy = o0 >> 5;

    // top-left source patch of output o0; o1's sources are s0+2, s0+3 (+64,+65)
    int s0 = (oy * 2) * GRID_ + ox * 2;

    const float4* base = in + ((size_t)b * S_ + s0) * C4_ + c;

    // 8 independent streaming loads, front-batched
    float4 r0 = __ldcs(base + 0 * C4_);               // s0      -> o0
    float4 r1 = __ldcs(base + 1 * C4_);               // s0+1    -> o0
    float4 r2 = __ldcs(base + 2 * C4_);               // s0+2    -> o1
    float4 r3 = __ldcs(base + 3 * C4_);               // s0+3    -> o1
    float4 r4 = __ldcs(base + (size_t)(GRID_ + 0) * C4_); // s0+64 -> o0
    float4 r5 = __ldcs(base + (size_t)(GRID_ + 1) * C4_); // s0+65 -> o0
    float4 r6 = __ldcs(base + (size_t)(GRID_ + 2) * C4_); // s0+66 -> o1
    float4 r7 = __ldcs(base + (size_t)(GRID_ + 3) * C4_); // s0+67 -> o1

    float4 w0, w1;
    w0.x = ((r0.x + r1.x) + (r4.x + r5.x)) * SCALE_;
    w0.y = ((r0.y + r1.y) + (r4.y + r5.y)) * SCALE_;
    w0.z = ((r0.z + r1.z) + (r4.z + r5.z)) * SCALE_;
    w0.w = ((r0.w + r1.w) + (r4.w + r5.w)) * SCALE_;
    w1.x = ((r2.x + r3.x) + (r6.x + r7.x)) * SCALE_;
    w1.y = ((r2.y + r3.y) + (r6.y + r7.y)) * SCALE_;
    w1.z = ((r2.z + r3.z) + (r6.z + r7.z)) * SCALE_;
    w1.w = ((r2.w + r3.w) + (r6.w + r7.w)) * SCALE_;

    float4* outp = out + ((size_t)b * L_ + o0) * C4_ + c;
    __stcs(outp, w0);
    __stcs(outp + C4_, w1);

    // fused mask write: first MASK_ELEMS_ threads each write one 1.0f
    if (write_mask && idx < MASK_ELEMS_) {
        mask_tail[idx] = 1.0f;
    }
}

extern "C" void kernel_launch(void* const* d_in, const int* in_sizes, int n_in,
                              void* d_out, int out_size) {
    const float4* in = (const float4*)d_in[0];
    float4* out = (float4*)d_out;

    int write_mask = (out_size > OUT_ELEMS_) ? 1 : 0;
    float* mask_tail = (float*)d_out + OUT_ELEMS_;

    constexpr int total_pairs = B_ * (L_ / 2) * C4_;
    constexpr int threads = 256;
    constexpr int blocks = (total_pairs + threads - 1) / threads;
    pool2x2_x2_kernel<<<blocks, threads>>>(in, out, mask_tail, write_mask);
}

// round 5
// speedup vs baseline: 1.1648x; 1.0930x over previous
#include <cuda_runtime.h>
#include <cuda_bf16.h>
#include <math.h>

// TorchGemma4VisionPooler: 2x2 average pool over a dense 64x64 patch grid,
// scaled by sqrt(H). B=8, S=4096, H=1152, OUT_LEN=1024.
//
// R4 (resubmit; previous attempt hit infra GPU-acquisition timeout):
// persistent grid-stride kernel — exactly one resident wave (148 SMs x
// 8 CTAs x 256 thr), removing ~3 inter-wave transitions and last-wave tail
// imbalance. Per iteration: 8 front-batched streaming LDG.128 (two output
// patches), 2 coalesced STG.128. Traffic 189 MB, DRAM-bound.

static constexpr int B_ = 8;
static constexpr int GRID_ = 64;
static constexpr int S_ = GRID_ * GRID_;     // 4096
static constexpr int H_ = 1152;
static constexpr int C4_ = H_ / 4;           // 288 float4 per row
static constexpr int OG_ = 32;               // output grid 32x32
static constexpr int L_ = OG_ * OG_;         // 1024
static constexpr int OUT_ELEMS_ = B_ * L_ * H_;  // 9437184
static constexpr int MASK_ELEMS_ = B_ * L_;      // 8192

static constexpr int THREADS_ = 256;
static constexpr int BLOCKS_ = 148 * 8;          // one full resident wave
static constexpr int STRIDE_ = THREADS_ * BLOCKS_;  // 303104

// sqrt(1152)/4
static constexpr float SCALE_ = 8.485281374238570f;

__global__ __launch_bounds__(THREADS_, 8)
void pool2x2_persist_kernel(const float4* __restrict__ in,
                            float4* __restrict__ out,
                            float* __restrict__ mask_tail,
                            int write_mask) {
    constexpr int total_pairs = B_ * (L_ / 2) * C4_;   // 1,179,648
    int tid0 = blockIdx.x * THREADS_ + threadIdx.x;

    // fused mask write: first MASK_ELEMS_ threads each write one 1.0f
    if (write_mask && tid0 < MASK_ELEMS_) {
        mask_tail[tid0] = 1.0f;
    }

    #pragma unroll 1
    for (int idx = tid0; idx < total_pairs; idx += STRIDE_) {
        int c = idx % C4_;
        int r = idx / C4_;          // r in [0, B*512)
        int op = r % (L_ / 2);      // output-pair index in [0,512)
        int b  = r / (L_ / 2);

        int o0 = op * 2;            // even output index; o1 = o0+1 shares oy
        int ox = o0 & (OG_ - 1);    // even, in [0,30]
        int oy = o0 >> 5;

        // top-left source patch of output o0; o1 pools s0+2..3 (+64 row)
        int s0 = (oy * 2) * GRID_ + ox * 2;

        const float4* base = in + ((size_t)b * S_ + s0) * C4_ + c;

        // 8 independent streaming loads, front-batched
        float4 r0 = __ldcs(base + 0 * C4_);
        float4 r1 = __ldcs(base + 1 * C4_);
        float4 r2 = __ldcs(base + 2 * C4_);
        float4 r3 = __ldcs(base + 3 * C4_);
        float4 r4 = __ldcs(base + (size_t)(GRID_ + 0) * C4_);
        float4 r5 = __ldcs(base + (size_t)(GRID_ + 1) * C4_);
        float4 r6 = __ldcs(base + (size_t)(GRID_ + 2) * C4_);
        float4 r7 = __ldcs(base + (size_t)(GRID_ + 3) * C4_);

        float4 w0, w1;
        w0.x = ((r0.x + r1.x) + (r4.x + r5.x)) * SCALE_;
        w0.y = ((r0.y + r1.y) + (r4.y + r5.y)) * SCALE_;
        w0.z = ((r0.z + r1.z) + (r4.z + r5.z)) * SCALE_;
        w0.w = ((r0.w + r1.w) + (r4.w + r5.w)) * SCALE_;
        w1.x = ((r2.x + r3.x) + (r6.x + r7.x)) * SCALE_;
        w1.y = ((r2.y + r3.y) + (r6.y + r7.y)) * SCALE_;
        w1.z = ((r2.z + r3.z) + (r6.z + r7.z)) * SCALE_;
        w1.w = ((r2.w + r3.w) + (r6.w + r7.w)) * SCALE_;

        float4* outp = out + ((size_t)b * L_ + o0) * C4_ + c;
        __stcs(outp, w0);
        __stcs(outp + C4_, w1);
    }
}

extern "C" void kernel_launch(void* const* d_in, const int* in_sizes, int n_in,
                              void* d_out, int out_size) {
    const float4* in = (const float4*)d_in[0];
    float4* out = (float4*)d_out;

    int write_mask = (out_size > OUT_ELEMS_) ? 1 : 0;
    float* mask_tail = (float*)d_out + OUT_ELEMS_;

    pool2x2_persist_kernel<<<BLOCKS_, THREADS_>>>(in, out, mask_tail, write_mask);
}